// round 5
// baseline (speedup 1.0000x reference)
#include <cuda_runtime.h>

#define THREADS 256
#define WARPS_PER_BLOCK (THREADS / 32)
#define MAX_PART 8192

__device__ float g_partials[MAX_PART];
__device__ unsigned int g_count = 0;   // wraps to 0 each replay via atomicInc

__global__ __launch_bounds__(THREADS) void yolo_loss_kernel(
    const float* __restrict__ pred,   // [n_cells, 30]
    const float* __restrict__ targ,   // [n_cells, 25]
    long n_cells,
    float* __restrict__ out)
{
    const int tid  = threadIdx.x;
    const int lane = tid & 31;
    const int wid  = tid >> 5;

    // one warp = one tile of 32 consecutive cells
    const long tile = (long)blockIdx.x * WARPS_PER_BLOCK + wid;
    const long cell0 = tile * 32;
    const long mycell = cell0 + lane;

    float acc = 0.0f;

    if (cell0 < n_cells) {
        bool valid = (mycell < n_cells);

        // ---- cheap scattered confidence loads (3 independent LDGs, high MLP) ----
        float c  = valid ? __ldg(targ + mycell * 25 + 4) : 0.0f;
        float c1 = valid ? __ldg(pred + mycell * 30 + 4) : 0.0f;
        float c2 = valid ? __ldg(pred + mycell * 30 + 9) : 0.0f;

        bool present = valid && (c == 1.0f);

        // absent cells: only objectness-absent term, no more bytes needed
        if (valid && !present)
            acc += 0.5f * fmaf(c1, c1, c2 * c2);

        unsigned m = __ballot_sync(0xFFFFFFFFu, present);

        // ---- software-pipelined cooperative loop over present cells ----
        float p_cur = 0.0f, t_cur = 0.0f;
        int have = 0;
        if (m) {
            int idx = __ffs(m) - 1; m &= m - 1;
            long cc = cell0 + idx;
            p_cur = (lane < 30) ? __ldg(pred + cc * 30 + lane) : 0.0f;
            t_cur = (lane < 25) ? __ldg(targ + cc * 25 + lane) : 0.0f;
            have = 1;
        }
        while (have) {
            float p = p_cur, t = t_cur;
            // prefetch next present cell's rows (dense, coalesced)
            if (m) {
                int idx = __ffs(m) - 1; m &= m - 1;
                long cc = cell0 + idx;
                p_cur = (lane < 30) ? __ldg(pred + cc * 30 + lane) : 0.0f;
                t_cur = (lane < 25) ? __ldg(targ + cc * 25 + lane) : 0.0f;
            } else {
                have = 0;
            }

            // ---- compute current cell cooperatively ----
            float p4 = __shfl_sync(0xFFFFFFFFu, p, 4);
            float p9 = __shfl_sync(0xFFFFFFFFu, p, 9);
            float tc = __shfl_sync(0xFFFFFFFFu, t, 4);
            bool  r1 = (p4 > p9);
            int   o  = r1 ? 0 : 5;

            int src;
            if (lane >= 10 && lane < 30) src = lane - 5;  // cls: T[5..24]
            else                         src = (lane - o) & 31;  // box: T[0..3]
            float tsh = __shfl_sync(0xFFFFFFFFu, t, src);

            float term = 0.0f;
            if (lane >= 10 && lane < 30) {            // class loss
                float d = p - tsh;
                term = d * d;
            } else if (lane >= o && lane < o + 2) {   // box centers
                float d = p - tsh;
                term = 5.0f * d * d;
            } else if (lane >= o + 2 && lane < o + 4) { // box h/w (sqrt)
                float d = sqrtf(p) - sqrtf(tsh);
                term = 5.0f * d * d;
            } else if (lane == 31) {                  // objectness present
                float d = (r1 ? p4 : p9) - tc;
                term = d * d;
            }
            acc += term;
        }
    }

    // ---- warp reduce ----
    #pragma unroll
    for (int off = 16; off > 0; off >>= 1)
        acc += __shfl_xor_sync(0xFFFFFFFFu, acc, off);

    __shared__ float wsum[WARPS_PER_BLOCK];
    if (lane == 0) wsum[wid] = acc;
    __syncthreads();

    __shared__ int s_last;
    if (tid == 0) {
        float b = 0.0f;
        #pragma unroll
        for (int i = 0; i < WARPS_PER_BLOCK; ++i) b += wsum[i];
        g_partials[blockIdx.x] = b;
        __threadfence();
        unsigned old = atomicInc(&g_count, gridDim.x - 1);
        s_last = (old == gridDim.x - 1) ? 1 : 0;
    }
    __syncthreads();

    // ---- last-arriving block: final reduction ----
    if (s_last) {
        __threadfence();
        double d = 0.0;
        for (int i = tid; i < (int)gridDim.x; i += THREADS)
            d += (double)__ldcg(&g_partials[i]);
        #pragma unroll
        for (int off = 16; off > 0; off >>= 1)
            d += __shfl_xor_sync(0xFFFFFFFFu, d, off);
        __shared__ double dsum[WARPS_PER_BLOCK];
        if (lane == 0) dsum[wid] = d;
        __syncthreads();
        if (tid == 0) {
            double s = 0.0;
            #pragma unroll
            for (int i = 0; i < WARPS_PER_BLOCK; ++i) s += dsum[i];
            out[0] = (float)s;
        }
    }
}

extern "C" void kernel_launch(void* const* d_in, const int* in_sizes, int n_in,
                              void* d_out, int out_size) {
    const float* pred = (const float*)d_in[0];   // [B, 1470]
    const float* targ = (const float*)d_in[1];   // [B, 1225]
    float* out = (float*)d_out;

    long B = (long)in_sizes[0] / 1470;
    long n_cells = B * 49;

    long n_tiles = (n_cells + 31) / 32;
    long blocks = (n_tiles + WARPS_PER_BLOCK - 1) / WARPS_PER_BLOCK;
    if (blocks > MAX_PART) blocks = MAX_PART;   // not hit at B=16384 (3136 blocks)

    yolo_loss_kernel<<<(unsigned)blocks, THREADS>>>(pred, targ, n_cells, out);
}

// round 6
// speedup vs baseline: 1.7177x; 1.7177x over previous
#include <cuda_runtime.h>
#include <cuda_pipeline.h>

#define THREADS 128
#define WPB     4             // warps per block
#define CPT     32            // cells per warp-tile
#define STAGES  2
#define PF      (CPT * 30)    // 960 floats pred per tile
#define TF      (CPT * 25)    // 800 floats targ per tile
#define MAX_PART 2048

__device__ float g_partials[MAX_PART];
__device__ unsigned int g_count = 0;   // wraps to 0 each replay via atomicInc

__global__ __launch_bounds__(THREADS) void yolo_loss_kernel(
    const float* __restrict__ pred,   // [n_cells, 30]
    const float* __restrict__ targ,   // [n_cells, 25]
    long n_cells,
    long n_tiles,
    float* __restrict__ out)
{
    // per-warp private double-buffered staging: 4 warps x 2 x 7040 B = 56.3 KB
    __shared__ __align__(16) float sP[WPB][STAGES][PF];
    __shared__ __align__(16) float sT[WPB][STAGES][TF];

    const int tid  = threadIdx.x;
    const int lane = tid & 31;
    const int wid  = tid >> 5;

    const long total_warps = (long)gridDim.x * WPB;
    const long warp_g = (long)blockIdx.x * WPB + wid;

    // warp-private async stage of one tile into slot
    auto stage = [&](int slot, long tile) {
        if (tile < n_tiles) {
            long cb = tile * CPT;
            int cells = (int)min((long)CPT, n_cells - cb);
            int npf = cells * 30, ntf = cells * 25;
            int np4 = npf >> 2, nt4 = ntf >> 2;
            const float4* gp = reinterpret_cast<const float4*>(pred + cb * 30); // tile*3840B: 16-aligned
            const float4* gt = reinterpret_cast<const float4*>(targ + cb * 25); // tile*3200B: 16-aligned
            float4* spp = reinterpret_cast<float4*>(sP[wid][slot]);
            float4* stt = reinterpret_cast<float4*>(sT[wid][slot]);
            for (int i = lane; i < np4; i += 32)
                __pipeline_memcpy_async(&spp[i], &gp[i], 16);
            for (int i = lane; i < nt4; i += 32)
                __pipeline_memcpy_async(&stt[i], &gt[i], 16);
            // ragged-tail floats (only possible on the final tile)
            for (int i = (np4 << 2) + lane; i < npf; i += 32)
                __pipeline_memcpy_async(&sP[wid][slot][i], &pred[cb * 30 + i], 4);
            for (int i = (nt4 << 2) + lane; i < ntf; i += 32)
                __pipeline_memcpy_async(&sT[wid][slot][i], &targ[cb * 25 + i], 4);
        }
        __pipeline_commit();
    };

    float acc = 0.0f;

    long tile = warp_g;
    stage(0, tile);                 // prologue

    int it = 0;
    while (tile < n_tiles) {
        stage((it + 1) & 1, tile + total_warps);   // prefetch next
        __pipeline_wait_prior(1);                  // current tile resident
        __syncwarp();

        int slot = it & 1;
        long cb = tile * CPT;
        int cells = (int)min((long)CPT, n_cells - cb);
        if (lane < cells) {
            const float* P = sP[wid][slot] + lane * 30;
            const float* T = sT[wid][slot] + lane * 25;

            float c1 = P[4];
            float c2 = P[9];
            float c  = T[4];
            bool present = (c == 1.0f);
            bool r1 = (c1 > c2);

            if (present) {
                float dobj = (r1 ? c1 : c2) - c;
                float loss = dobj * dobj;

                float cls = 0.0f;
                #pragma unroll
                for (int i = 0; i < 20; ++i) {
                    float d = P[10 + i] - T[5 + i];
                    cls = fmaf(d, d, cls);
                }

                int o = r1 ? 0 : 5;
                float box = 0.0f;
                #pragma unroll
                for (int i = 0; i < 2; ++i) {
                    float d = P[o + i] - T[i];
                    box = fmaf(d, d, box);
                }
                #pragma unroll
                for (int i = 0; i < 2; ++i) {
                    float d = sqrtf(P[o + 2 + i]) - sqrtf(T[2 + i]);
                    box = fmaf(d, d, box);
                }
                acc += loss + cls + 5.0f * box;
            } else {
                acc += 0.5f * fmaf(c1, c1, c2 * c2);
            }
        }
        __syncwarp();               // all lanes done reading before slot refill
        tile += total_warps;
        ++it;
    }

    // ---- warp reduce, then block partial ----
    #pragma unroll
    for (int off = 16; off > 0; off >>= 1)
        acc += __shfl_xor_sync(0xFFFFFFFFu, acc, off);

    __shared__ float wsum[WPB];
    if (lane == 0) wsum[wid] = acc;
    __syncthreads();

    __shared__ int s_last;
    if (tid == 0) {
        g_partials[blockIdx.x] = wsum[0] + wsum[1] + wsum[2] + wsum[3];
        __threadfence();
        unsigned old = atomicInc(&g_count, gridDim.x - 1);
        s_last = (old == gridDim.x - 1) ? 1 : 0;
    }
    __syncthreads();

    // ---- last-arriving block: final reduction, write scalar ----
    if (s_last) {
        __threadfence();
        double d = 0.0;
        for (int i = tid; i < (int)gridDim.x; i += THREADS)
            d += (double)__ldcg(&g_partials[i]);
        #pragma unroll
        for (int off = 16; off > 0; off >>= 1)
            d += __shfl_xor_sync(0xFFFFFFFFu, d, off);
        __shared__ double dsum[WPB];
        if (lane == 0) dsum[wid] = d;
        __syncthreads();
        if (tid == 0)
            out[0] = (float)(dsum[0] + dsum[1] + dsum[2] + dsum[3]);
    }
}

extern "C" void kernel_launch(void* const* d_in, const int* in_sizes, int n_in,
                              void* d_out, int out_size) {
    const float* pred = (const float*)d_in[0];   // [B, 1470]
    const float* targ = (const float*)d_in[1];   // [B, 1225]
    float* out = (float*)d_out;

    long B = (long)in_sizes[0] / 1470;
    long n_cells = B * 49;
    long n_tiles = (n_cells + CPT - 1) / CPT;

    // 4 blocks/SM x 148 SMs (56.3 KB smem each -> 225 KB/SM)
    long blocks = 148L * 4;
    if (blocks * WPB > n_tiles) blocks = (n_tiles + WPB - 1) / WPB;
    if (blocks > MAX_PART) blocks = MAX_PART;

    yolo_loss_kernel<<<(unsigned)blocks, THREADS>>>(pred, targ, n_cells, n_tiles, out);
}